// round 13
// baseline (speedup 1.0000x reference)
#include <cuda_runtime.h>
#include <cuda_bf16.h>
#include <cuda_fp16.h>
#include <cstdint>
#include <cstddef>

#define NN 50000
#define EE 1250000
#define HH 64
#define DD 128
#define GG 128
#define CC 10
#define LL 2
#define TILES128 391      // ceil(NN/128)
#define SA 72             // row stride in bf16 elements
#define SAB 144           // row stride in bytes (9 x 16B -> LDSM conflict-free)
#define BK 128            // bucket capacity per node (deg ~ Poisson(25), 20 sigma)

// SMEM layout (dynamic):
#define OFF_AHI 0
#define OFF_ALO (128 * SAB)
#define OFF_W   (2 * 128 * SAB)
#define TILE_B  (64 * SAB)
#define WT(i)   (OFF_W + (i) * TILE_B)

// ---------------- scratch (static __device__, no allocation) ----------------
__device__ __align__(16) float  g_h[NN * HH];
__device__ __align__(16) __half g_hf[NN * HH];   // fp16 mirror: agg gather source
__device__ __align__(16) float  g_agg[NN * HH];
__device__ __align__(16) float  g_pooled[GG * HH];

__device__ int g_cnt[NN];
__device__ int g_bucket[(size_t)NN * BK];   // 25.6 MB edge buckets

// ================= bucket build =================
__global__ void zero_cnt_kernel() {
    int i = blockIdx.x * blockDim.x + threadIdx.x;
    if (i < NN) g_cnt[i] = 0;
}
__global__ void fill_bucket_kernel(const int* __restrict__ ei) {
    int e = blockIdx.x * blockDim.x + threadIdx.x;
    if (e >= EE) return;
    int s = ei[e];
    int d = ei[EE + e];
    int pos = atomicAdd(&g_cnt[d], 1);
    if (pos < BK) g_bucket[((size_t)d << 7) + pos] = s;
}

// ================= aggregation: fp16 gather (1 line per edge) ==============
__global__ void __launch_bounds__(256) agg_kernel() {
    int wid = (blockIdx.x * blockDim.x + threadIdx.x) >> 5;
    if (wid >= NN) return;
    int lane = threadIdx.x & 31;
    int half = lane >> 4;
    int l16 = lane & 15;

    int deg = g_cnt[wid];
    int n = (deg < BK) ? deg : BK;
    const int* bkt = g_bucket + ((size_t)wid << 7);

    float4 acc = make_float4(0.f, 0.f, 0.f, 0.f);
    for (int e = half; e < n; e += 2) {
        int s = bkt[e];
        uint2 u = *(const uint2*)(g_hf + (size_t)s * HH + (l16 << 2));
        float2 f0 = __half22float2(*(const __half2*)&u.x);
        float2 f1 = __half22float2(*(const __half2*)&u.y);
        acc.x += f0.x; acc.y += f0.y; acc.z += f1.x; acc.w += f1.y;
    }
    acc.x += __shfl_down_sync(0xffffffffu, acc.x, 16);
    acc.y += __shfl_down_sync(0xffffffffu, acc.y, 16);
    acc.z += __shfl_down_sync(0xffffffffu, acc.z, 16);
    acc.w += __shfl_down_sync(0xffffffffu, acc.w, 16);

    if (half == 0) {
        float inv = 1.0f / fmaxf((float)deg, 1.0f);
        acc.x *= inv; acc.y *= inv; acc.z *= inv; acc.w *= inv;
        *(float4*)(g_agg + (size_t)wid * HH + (l16 << 2)) = acc;
    }
}

// ================= bf16 split + MMA + LDSM helpers (proven) ================
__device__ __forceinline__ void split2(float a, float b, uint32_t& hi, uint32_t& lo) {
    __nv_bfloat16 ha = __float2bfloat16(a), hb = __float2bfloat16(b);
    float ra = a - __bfloat162float(ha);
    float rb = b - __bfloat162float(hb);
    __nv_bfloat16 la = __float2bfloat16(ra), lb = __float2bfloat16(rb);
    hi = (uint32_t)__bfloat16_as_ushort(ha) | ((uint32_t)__bfloat16_as_ushort(hb) << 16);
    lo = (uint32_t)__bfloat16_as_ushort(la) | ((uint32_t)__bfloat16_as_ushort(lb) << 16);
}

__device__ __forceinline__ void mma_bf16(float* acc,
                                         uint32_t a0, uint32_t a1, uint32_t a2, uint32_t a3,
                                         uint32_t b0, uint32_t b1) {
    asm volatile(
        "mma.sync.aligned.m16n8k16.row.col.f32.bf16.bf16.f32 "
        "{%0,%1,%2,%3}, {%4,%5,%6,%7}, {%8,%9}, {%0,%1,%2,%3};"
        : "+f"(acc[0]), "+f"(acc[1]), "+f"(acc[2]), "+f"(acc[3])
        : "r"(a0), "r"(a1), "r"(a2), "r"(a3), "r"(b0), "r"(b1));
}

__device__ __forceinline__ void ldsm4(uint32_t addr,
                                      uint32_t& r0, uint32_t& r1,
                                      uint32_t& r2, uint32_t& r3) {
    asm volatile("ldmatrix.sync.aligned.m8n8.x4.shared.b16 {%0,%1,%2,%3}, [%4];"
                 : "=r"(r0), "=r"(r1), "=r"(r2), "=r"(r3) : "r"(addr));
}

// ================= staging =================
__device__ __forceinline__ void stage_W(char* sm, int hi_off, int lo_off,
                                        const float* __restrict__ W, int kbase) {
    int tid = threadIdx.x;
    int n = tid >> 2;
    int kc = (tid & 3) * 16;
    uint32_t* hi = (uint32_t*)(sm + hi_off + (size_t)n * SAB + kc * 2);
    uint32_t* lo = (uint32_t*)(sm + lo_off + (size_t)n * SAB + kc * 2);
#pragma unroll
    for (int p = 0; p < 8; p++) {
        int k = kc + 2 * p;
        float a = W[(size_t)(kbase + k) * 64 + n];
        float b = W[(size_t)(kbase + k + 1) * 64 + n];
        uint32_t h, l;
        split2(a, b, h, l);
        hi[p] = h; lo[p] = l;
    }
}

__device__ __forceinline__ void stage_A_w(char* sm, const float* __restrict__ A,
                                          int row0, int K, int kofs,
                                          int m0, int lane) {
    int r = m0 + (lane & 15);
    int cb = (lane >> 4) << 5;
    int row = row0 + r;
#pragma unroll
    for (int cc = 0; cc < 2; cc++) {
        int c0 = cb + cc * 16;
        float v[16];
        if (row < NN) {
            const float* src = A + (size_t)row * K + kofs + c0;
#pragma unroll
            for (int q = 0; q < 4; q++) {
                float4 f = *(const float4*)(src + q * 4);
                v[q * 4 + 0] = f.x; v[q * 4 + 1] = f.y;
                v[q * 4 + 2] = f.z; v[q * 4 + 3] = f.w;
            }
        } else {
#pragma unroll
            for (int q = 0; q < 16; q++) v[q] = 0.f;
        }
        uint4 h0, h1, l0, l1;
        split2(v[0],  v[1],  h0.x, l0.x); split2(v[2],  v[3],  h0.y, l0.y);
        split2(v[4],  v[5],  h0.z, l0.z); split2(v[6],  v[7],  h0.w, l0.w);
        split2(v[8],  v[9],  h1.x, l1.x); split2(v[10], v[11], h1.y, l1.y);
        split2(v[12], v[13], h1.z, l1.z); split2(v[14], v[15], h1.w, l1.w);
        char* ph = sm + OFF_AHI + (size_t)r * SAB + c0 * 2;
        char* pl = sm + OFF_ALO + (size_t)r * SAB + c0 * 2;
        ((uint4*)ph)[0] = h0; ((uint4*)ph)[1] = h1;
        ((uint4*)pl)[0] = l0; ((uint4*)pl)[1] = l1;
    }
}

__device__ __forceinline__ void gemm_unit_w(uint32_t smb, int wt_hi, int wt_lo,
                                            float* acc, int m0, int lane) {
    uint32_t aoff = (uint32_t)((m0 + (lane & 15)) * SAB + ((lane >> 4) << 4));
    uint32_t boff = (uint32_t)(((lane & 7) + ((lane >> 4) << 3)) * SAB
                               + (((lane >> 3) & 1) << 4));
    uint32_t a_hi = smb + OFF_AHI + aoff;
    uint32_t a_lo = smb + OFF_ALO + aoff;
    uint32_t b_hi = smb + wt_hi + boff;
    uint32_t b_lo = smb + wt_lo + boff;

#pragma unroll
    for (int ks = 0; ks < 4; ks++) {
        uint32_t ah0, ah1, ah2, ah3, al0, al1, al2, al3;
        ldsm4(a_hi + ks * 32, ah0, ah1, ah2, ah3);
        ldsm4(a_lo + ks * 32, al0, al1, al2, al3);
#pragma unroll
        for (int p = 0; p < 4; p++) {
            uint32_t b0, b1, b2, b3, c0, c1, c2, c3;
            ldsm4(b_hi + p * (16 * SAB) + ks * 32, b0, b1, b2, b3);
            ldsm4(b_lo + p * (16 * SAB) + ks * 32, c0, c1, c2, c3);
            float* A0 = acc + (2 * p) * 4;
            float* A1 = acc + (2 * p + 1) * 4;
            mma_bf16(A0, ah0, ah1, ah2, ah3, b0, b1);
            mma_bf16(A1, ah0, ah1, ah2, ah3, b2, b3);
            mma_bf16(A0, ah0, ah1, ah2, ah3, c0, c1);
            mma_bf16(A1, ah0, ah1, ah2, ah3, c2, c3);
            mma_bf16(A0, al0, al1, al2, al3, b0, b1);
            mma_bf16(A1, al0, al1, al2, al3, b2, b3);
        }
    }
}

__device__ __forceinline__ void zero32(float* a) {
#pragma unroll
    for (int i = 0; i < 32; i++) a[i] = 0.f;
}

__device__ __forceinline__ void epi_to_A_w(char* sm, const float* acc,
                                           const float* __restrict__ bias,
                                           bool relu, int m0, int lane) {
    int g = lane >> 2, tg = lane & 3;
    size_t r0 = (size_t)(m0 + g) * SAB;
    size_t r1 = (size_t)(m0 + g + 8) * SAB;
#pragma unroll
    for (int j = 0; j < 8; j++) {
        int col = j * 8 + tg * 2;
        float b0 = __ldg(bias + col), b1 = __ldg(bias + col + 1);
        float v00 = acc[j * 4 + 0] + b0, v01 = acc[j * 4 + 1] + b1;
        float v10 = acc[j * 4 + 2] + b0, v11 = acc[j * 4 + 3] + b1;
        if (relu) {
            v00 = fmaxf(v00, 0.f); v01 = fmaxf(v01, 0.f);
            v10 = fmaxf(v10, 0.f); v11 = fmaxf(v11, 0.f);
        }
        uint32_t h, l;
        split2(v00, v01, h, l);
        *(uint32_t*)(sm + OFF_AHI + r0 + col * 2) = h;
        *(uint32_t*)(sm + OFF_ALO + r0 + col * 2) = l;
        split2(v10, v11, h, l);
        *(uint32_t*)(sm + OFF_AHI + r1 + col * 2) = h;
        *(uint32_t*)(sm + OFF_ALO + r1 + col * 2) = l;
    }
}

// final epilogue: fp32 g_h + fp16 g_hf mirror
__device__ __forceinline__ void epi_to_gmem_w(const float* acc,
                                              const float* __restrict__ bias,
                                              bool relu, int row0, int m0, int lane) {
    int g = lane >> 2, tg = lane & 3;
    int ra = row0 + m0 + g;
    int rb = ra + 8;
#pragma unroll
    for (int j = 0; j < 8; j++) {
        int col = j * 8 + tg * 2;
        float b0 = __ldg(bias + col), b1 = __ldg(bias + col + 1);
        float v00 = acc[j * 4 + 0] + b0, v01 = acc[j * 4 + 1] + b1;
        float v10 = acc[j * 4 + 2] + b0, v11 = acc[j * 4 + 3] + b1;
        if (relu) {
            v00 = fmaxf(v00, 0.f); v01 = fmaxf(v01, 0.f);
            v10 = fmaxf(v10, 0.f); v11 = fmaxf(v11, 0.f);
        }
        if (ra < NN) {
            *(float2*)(g_h + (size_t)ra * 64 + col) = make_float2(v00, v01);
            *(__half2*)(g_hf + (size_t)ra * 64 + col) = __floats2half2_rn(v00, v01);
        }
        if (rb < NN) {
            *(float2*)(g_h + (size_t)rb * 64 + col) = make_float2(v10, v11);
            *(__half2*)(g_hf + (size_t)rb * 64 + col) = __floats2half2_rn(v10, v11);
        }
    }
}

// ================= fused embed MLP =================
__global__ void __launch_bounds__(256) embed_kernel(
    const float* __restrict__ x,
    const float* __restrict__ w1, const float* __restrict__ b1,
    const float* __restrict__ w2, const float* __restrict__ b2)
{
    extern __shared__ char sm[];
    uint32_t smb = (uint32_t)__cvta_generic_to_shared(sm);
    int lane = threadIdx.x & 31;
    int m0 = (threadIdx.x >> 5) * 16;
    int row0 = blockIdx.x * 128;

    stage_W(sm, WT(0), WT(1), w1, 0);
    stage_W(sm, WT(2), WT(3), w1, 64);
    stage_W(sm, WT(4), WT(5), w2, 0);
    __syncthreads();

    float acc[32];
    zero32(acc);
    stage_A_w(sm, x, row0, DD, 0, m0, lane);
    __syncwarp();
    gemm_unit_w(smb, WT(0), WT(1), acc, m0, lane);
    __syncwarp();
    stage_A_w(sm, x, row0, DD, 64, m0, lane);
    __syncwarp();
    gemm_unit_w(smb, WT(2), WT(3), acc, m0, lane);
    __syncwarp();
    epi_to_A_w(sm, acc, b1, true, m0, lane);
    __syncwarp();

    zero32(acc);
    gemm_unit_w(smb, WT(4), WT(5), acc, m0, lane);
    epi_to_gmem_w(acc, b2, false, row0, m0, lane);
}

// ================= fused conv layer =================
__global__ void __launch_bounds__(256) layer_kernel(
    const float* __restrict__ rw, const float* __restrict__ rb,
    const float* __restrict__ ow,
    const float* __restrict__ pw1, const float* __restrict__ pb1,
    const float* __restrict__ pw2, const float* __restrict__ pb2)
{
    extern __shared__ char sm[];
    uint32_t smb = (uint32_t)__cvta_generic_to_shared(sm);
    int lane = threadIdx.x & 31;
    int m0 = (threadIdx.x >> 5) * 16;
    int row0 = blockIdx.x * 128;

    stage_W(sm, WT(0), WT(1), rw, 0);
    stage_W(sm, WT(2), WT(3), ow, 0);
    stage_W(sm, WT(4), WT(5), pw1, 0);
    stage_W(sm, WT(6), WT(7), pw2, 0);
    __syncthreads();

    float acc[32];
    zero32(acc);
    stage_A_w(sm, g_agg, row0, HH, 0, m0, lane);
    __syncwarp();
    gemm_unit_w(smb, WT(0), WT(1), acc, m0, lane);
    __syncwarp();
    stage_A_w(sm, g_h, row0, HH, 0, m0, lane);
    __syncwarp();
    gemm_unit_w(smb, WT(2), WT(3), acc, m0, lane);
    __syncwarp();
    epi_to_A_w(sm, acc, rb, false, m0, lane);
    __syncwarp();

    zero32(acc);
    gemm_unit_w(smb, WT(4), WT(5), acc, m0, lane);
    __syncwarp();
    epi_to_A_w(sm, acc, pb1, true, m0, lane);
    __syncwarp();

    zero32(acc);
    gemm_unit_w(smb, WT(6), WT(7), acc, m0, lane);
    epi_to_gmem_w(acc, pb2, true, row0, m0, lane);
}

// ================= pooling + classifier =================
__device__ __forceinline__ int lbound(const int* a, int n, int v) {
    int lo = 0, hi = n;
    while (lo < hi) {
        int m = (lo + hi) >> 1;
        if (a[m] < v) lo = m + 1; else hi = m;
    }
    return lo;
}

__global__ void __launch_bounds__(256) pool_kernel(const int* __restrict__ batch) {
    __shared__ int s_lo, s_hi;
    __shared__ float sm[4][64];
    int g = blockIdx.x;
    int tid = threadIdx.x;
    if (tid == 0) {
        s_lo = lbound(batch, NN, g);
        s_hi = lbound(batch, NN, g + 1);
    }
    __syncthreads();
    int lo = s_lo, hi = s_hi;
    int col = tid & 63;
    int rg = tid >> 6;

    float acc = 0.f;
    for (int n = lo + rg; n < hi; n += 4)
        acc += g_h[(size_t)n * HH + col];
    sm[rg][col] = acc;
    __syncthreads();
    if (rg == 0) {
        float s = sm[0][col] + sm[1][col] + sm[2][col] + sm[3][col];
        float inv = 1.0f / fmaxf((float)(hi - lo), 1.0f);
        g_pooled[(size_t)g * HH + col] = s * inv;
    }
}

__global__ void cls_kernel(const float* __restrict__ W,
                           const float* __restrict__ b,
                           float* __restrict__ out)
{
    int tid = blockIdx.x * blockDim.x + threadIdx.x;
    if (tid >= GG * CC) return;
    int g = tid / CC;
    int c = tid % CC;
    float s = b[c];
#pragma unroll
    for (int k = 0; k < HH; k++)
        s += g_pooled[g * HH + k] * W[k * CC + c];
    out[tid] = s;
}

// ================= launcher =================
extern "C" void kernel_launch(void* const* d_in, const int* in_sizes, int n_in,
                              void* d_out, int out_size) {
    const float* x       = (const float*)d_in[0];
    const int*   ei      = (const int*)d_in[1];
    const int*   batch   = (const int*)d_in[2];
    const float* emb_w1  = (const float*)d_in[3];
    const float* emb_b1  = (const float*)d_in[4];
    const float* emb_w2  = (const float*)d_in[5];
    const float* emb_b2  = (const float*)d_in[6];
    const float* rel_w   = (const float*)d_in[7];
    const float* rel_b   = (const float*)d_in[8];
    const float* root_w  = (const float*)d_in[9];
    const float* post_w1 = (const float*)d_in[10];
    const float* post_b1 = (const float*)d_in[11];
    const float* post_w2 = (const float*)d_in[12];
    const float* post_b2 = (const float*)d_in[13];
    const float* cls_w   = (const float*)d_in[14];
    const float* cls_b   = (const float*)d_in[15];
    float*       out     = (float*)d_out;

    const int TB = 256;
    const int embed_smem = OFF_W + 6 * TILE_B;   // 92,160 B
    const int layer_smem = OFF_W + 8 * TILE_B;   // 110,592 B
    cudaFuncSetAttribute(embed_kernel, cudaFuncAttributeMaxDynamicSharedMemorySize, embed_smem);
    cudaFuncSetAttribute(layer_kernel, cudaFuncAttributeMaxDynamicSharedMemorySize, layer_smem);

    // ---- bucket build ----
    zero_cnt_kernel<<<(NN + TB - 1) / TB, TB>>>();
    fill_bucket_kernel<<<(EE + TB - 1) / TB, TB>>>(ei);

    // ---- embed; first agg stays at capture slot 3 for the profile ----
    embed_kernel<<<TILES128, 256, embed_smem>>>(x, emb_w1, emb_b1, emb_w2, emb_b2);

    for (int l = 0; l < LL; l++) {
        agg_kernel<<<(NN * 32 + TB - 1) / TB, TB>>>();
        layer_kernel<<<TILES128, 256, layer_smem>>>(
            rel_w   + (size_t)l * HH * HH,
            rel_b   + (size_t)l * HH,
            root_w  + (size_t)l * HH * HH,
            post_w1 + (size_t)l * HH * HH,
            post_b1 + (size_t)l * HH,
            post_w2 + (size_t)l * HH * HH,
            post_b2 + (size_t)l * HH);
    }

    // ---- mean pool + classifier ----
    pool_kernel<<<GG, 256>>>(batch);
    cls_kernel<<<(GG * CC + TB - 1) / TB, TB>>>(cls_w, cls_b, out);
}

// round 14
// speedup vs baseline: 1.1472x; 1.1472x over previous
#include <cuda_runtime.h>
#include <cuda_bf16.h>
#include <cstdint>
#include <cstddef>

#define NN 50000
#define EE 1250000
#define HH 64
#define DD 128
#define GG 128
#define CC 10
#define LL 2
#define TILES128 391      // ceil(NN/128)
#define SAB 144           // A row stride in bytes (9 x 16B -> LDSM conflict-free)
#define BK 128            // bucket capacity per node
#define NT_W 11           // weight tiles

// SMEM: A tiles only
#define OFF_AHI 0
#define OFF_ALO (128 * SAB)
#define A_SMEM  (2 * 128 * SAB)   // 36,864 B

// ---------------- scratch (static __device__, no allocation) ----------------
__device__ __align__(16) float g_h[NN * HH];
__device__ __align__(16) float g_agg[NN * HH];
__device__ __align__(16) float g_pooled[GG * HH];
__device__ __align__(16) uint4 g_wfrag[NT_W * 1024];   // fragment-ordered weights

__device__ int g_cnt[NN];
__device__ int g_bucket[(size_t)NN * BK];

// ================= bf16 split helper =================
__device__ __forceinline__ void split2(float a, float b, uint32_t& hi, uint32_t& lo) {
    __nv_bfloat16 ha = __float2bfloat16(a), hb = __float2bfloat16(b);
    float ra = a - __bfloat162float(ha);
    float rb = b - __bfloat162float(hb);
    __nv_bfloat16 la = __float2bfloat16(ra), lb = __float2bfloat16(rb);
    hi = (uint32_t)__bfloat16_as_ushort(ha) | ((uint32_t)__bfloat16_as_ushort(hb) << 16);
    lo = (uint32_t)__bfloat16_as_ushort(la) | ((uint32_t)__bfloat16_as_ushort(lb) << 16);
}

// ================= weight fragment prep (once per launch) =================
// tile t: fragment layout item = p*256 + ks*64 + plane*32 + lane (uint4 each)
// reg r of lane: n = p*16 + (r>=2 ? 8:0) + lane/4 ; k = ks*16 + (lane%4)*2 + (r&1 ? 8:0)
__global__ void __launch_bounds__(256) prep_wfrag_kernel(
    const float* __restrict__ emb_w1, const float* __restrict__ emb_w2,
    const float* __restrict__ rel_w,  const float* __restrict__ root_w,
    const float* __restrict__ pw1,    const float* __restrict__ pw2)
{
    int t = blockIdx.x;
    const float* W;
    int kbase = 0;
    if (t == 0)      { W = emb_w1; kbase = 0;  }
    else if (t == 1) { W = emb_w1; kbase = 64; }
    else if (t == 2) { W = emb_w2; }
    else {
        int l = (t - 3) >> 2;
        int w = (t - 3) & 3;
        size_t ofs = (size_t)l * HH * HH;
        W = (w == 0) ? rel_w + ofs : (w == 1) ? root_w + ofs
          : (w == 2) ? pw1 + ofs : pw2 + ofs;
    }
    for (int item = threadIdx.x; item < 1024; item += 256) {
        int lane  = item & 31;
        int plane = (item >> 5) & 1;
        int ks    = (item >> 6) & 3;
        int p     = (item >> 8) & 3;
        uint32_t vals[4];
#pragma unroll
        for (int r = 0; r < 4; r++) {
            int n = p * 16 + ((r >> 1) ? 8 : 0) + (lane >> 2);
            int k = ks * 16 + ((lane & 3) << 1) + ((r & 1) ? 8 : 0);
            float a = W[(size_t)(kbase + k) * 64 + n];
            float b = W[(size_t)(kbase + k + 1) * 64 + n];
            uint32_t hi, lo;
            split2(a, b, hi, lo);
            vals[r] = plane ? lo : hi;
        }
        g_wfrag[t * 1024 + item] = make_uint4(vals[0], vals[1], vals[2], vals[3]);
    }
}

// ================= bucket build =================
__global__ void zero_cnt_kernel() {
    int i = blockIdx.x * blockDim.x + threadIdx.x;
    if (i < NN) g_cnt[i] = 0;
}
__global__ void fill_bucket_kernel(const int* __restrict__ ei) {
    int e = blockIdx.x * blockDim.x + threadIdx.x;
    if (e >= EE) return;
    int s = ei[e];
    int d = ei[EE + e];
    int pos = atomicAdd(&g_cnt[d], 1);
    if (pos < BK) g_bucket[((size_t)d << 7) + pos] = s;
}

// ================= aggregation (R12 fp32, proven) =================
__global__ void __launch_bounds__(256) agg_kernel() {
    int wid = (blockIdx.x * blockDim.x + threadIdx.x) >> 5;
    if (wid >= NN) return;
    int lane = threadIdx.x & 31;
    int half = lane >> 4;
    int l16 = lane & 15;

    int deg = g_cnt[wid];
    int n = (deg < BK) ? deg : BK;
    const int* bkt = g_bucket + ((size_t)wid << 7);

    float4 acc = make_float4(0.f, 0.f, 0.f, 0.f);
    for (int e = half; e < n; e += 2) {
        int s = bkt[e];
        float4 v = *(const float4*)(g_h + (size_t)s * HH + (l16 << 2));
        acc.x += v.x; acc.y += v.y; acc.z += v.z; acc.w += v.w;
    }
    acc.x += __shfl_down_sync(0xffffffffu, acc.x, 16);
    acc.y += __shfl_down_sync(0xffffffffu, acc.y, 16);
    acc.z += __shfl_down_sync(0xffffffffu, acc.z, 16);
    acc.w += __shfl_down_sync(0xffffffffu, acc.w, 16);

    if (half == 0) {
        float inv = 1.0f / fmaxf((float)deg, 1.0f);
        acc.x *= inv; acc.y *= inv; acc.z *= inv; acc.w *= inv;
        *(float4*)(g_agg + (size_t)wid * HH + (l16 << 2)) = acc;
    }
}

// ================= MMA + LDSM =================
__device__ __forceinline__ void mma_bf16(float* acc,
                                         uint32_t a0, uint32_t a1, uint32_t a2, uint32_t a3,
                                         uint32_t b0, uint32_t b1) {
    asm volatile(
        "mma.sync.aligned.m16n8k16.row.col.f32.bf16.bf16.f32 "
        "{%0,%1,%2,%3}, {%4,%5,%6,%7}, {%8,%9}, {%0,%1,%2,%3};"
        : "+f"(acc[0]), "+f"(acc[1]), "+f"(acc[2]), "+f"(acc[3])
        : "r"(a0), "r"(a1), "r"(a2), "r"(a3), "r"(b0), "r"(b1));
}

__device__ __forceinline__ void ldsm4(uint32_t addr,
                                      uint32_t& r0, uint32_t& r1,
                                      uint32_t& r2, uint32_t& r3) {
    asm volatile("ldmatrix.sync.aligned.m8n8.x4.shared.b16 {%0,%1,%2,%3}, [%4];"
                 : "=r"(r0), "=r"(r1), "=r"(r2), "=r"(r3) : "r"(addr));
}

// ================= A staging (R11, proven) =================
__device__ __forceinline__ void stage_A_w(char* sm, const float* __restrict__ A,
                                          int row0, int K, int kofs,
                                          int m0, int lane) {
    int r = m0 + (lane & 15);
    int cb = (lane >> 4) << 5;
    int row = row0 + r;
#pragma unroll
    for (int cc = 0; cc < 2; cc++) {
        int c0 = cb + cc * 16;
        float v[16];
        if (row < NN) {
            const float* src = A + (size_t)row * K + kofs + c0;
#pragma unroll
            for (int q = 0; q < 4; q++) {
                float4 f = *(const float4*)(src + q * 4);
                v[q * 4 + 0] = f.x; v[q * 4 + 1] = f.y;
                v[q * 4 + 2] = f.z; v[q * 4 + 3] = f.w;
            }
        } else {
#pragma unroll
            for (int q = 0; q < 16; q++) v[q] = 0.f;
        }
        uint4 h0, h1, l0, l1;
        split2(v[0],  v[1],  h0.x, l0.x); split2(v[2],  v[3],  h0.y, l0.y);
        split2(v[4],  v[5],  h0.z, l0.z); split2(v[6],  v[7],  h0.w, l0.w);
        split2(v[8],  v[9],  h1.x, l1.x); split2(v[10], v[11], h1.y, l1.y);
        split2(v[12], v[13], h1.z, l1.z); split2(v[14], v[15], h1.w, l1.w);
        char* ph = sm + OFF_AHI + (size_t)r * SAB + c0 * 2;
        char* pl = sm + OFF_ALO + (size_t)r * SAB + c0 * 2;
        ((uint4*)ph)[0] = h0; ((uint4*)ph)[1] = h1;
        ((uint4*)pl)[0] = l0; ((uint4*)pl)[1] = l1;
    }
}

// ================= GEMM unit: A from smem (LDSM), B from g_wfrag (LDG) =====
__device__ __forceinline__ void gemm_unit_w(uint32_t smb, int t,
                                            float* acc, int m0, int lane) {
    const uint4* wf = g_wfrag + t * 1024 + lane;
    uint32_t aoff = (uint32_t)((m0 + (lane & 15)) * SAB + ((lane >> 4) << 4));
    uint32_t a_hi = smb + OFF_AHI + aoff;
    uint32_t a_lo = smb + OFF_ALO + aoff;

#pragma unroll
    for (int ks = 0; ks < 4; ks++) {
        uint32_t ah0, ah1, ah2, ah3, al0, al1, al2, al3;
        ldsm4(a_hi + ks * 32, ah0, ah1, ah2, ah3);
        ldsm4(a_lo + ks * 32, al0, al1, al2, al3);
#pragma unroll
        for (int p = 0; p < 4; p++) {
            uint4 bh = wf[(p * 4 + ks) * 64];        // plane 0 (uint4 index, lane folded)
            uint4 bl = wf[(p * 4 + ks) * 64 + 32];   // plane 1
            float* A0 = acc + (2 * p) * 4;
            float* A1 = acc + (2 * p + 1) * 4;
            mma_bf16(A0, ah0, ah1, ah2, ah3, bh.x, bh.y);
            mma_bf16(A1, ah0, ah1, ah2, ah3, bh.z, bh.w);
            mma_bf16(A0, ah0, ah1, ah2, ah3, bl.x, bl.y);
            mma_bf16(A1, ah0, ah1, ah2, ah3, bl.z, bl.w);
            mma_bf16(A0, al0, al1, al2, al3, bh.x, bh.y);
            mma_bf16(A1, al0, al1, al2, al3, bh.z, bh.w);
        }
    }
}

__device__ __forceinline__ void zero32(float* a) {
#pragma unroll
    for (int i = 0; i < 32; i++) a[i] = 0.f;
}

__device__ __forceinline__ void epi_to_A_w(char* sm, const float* acc,
                                           const float* __restrict__ bias,
                                           bool relu, int m0, int lane) {
    int g = lane >> 2, tg = lane & 3;
    size_t r0 = (size_t)(m0 + g) * SAB;
    size_t r1 = (size_t)(m0 + g + 8) * SAB;
#pragma unroll
    for (int j = 0; j < 8; j++) {
        int col = j * 8 + tg * 2;
        float b0 = __ldg(bias + col), b1 = __ldg(bias + col + 1);
        float v00 = acc[j * 4 + 0] + b0, v01 = acc[j * 4 + 1] + b1;
        float v10 = acc[j * 4 + 2] + b0, v11 = acc[j * 4 + 3] + b1;
        if (relu) {
            v00 = fmaxf(v00, 0.f); v01 = fmaxf(v01, 0.f);
            v10 = fmaxf(v10, 0.f); v11 = fmaxf(v11, 0.f);
        }
        uint32_t h, l;
        split2(v00, v01, h, l);
        *(uint32_t*)(sm + OFF_AHI + r0 + col * 2) = h;
        *(uint32_t*)(sm + OFF_ALO + r0 + col * 2) = l;
        split2(v10, v11, h, l);
        *(uint32_t*)(sm + OFF_AHI + r1 + col * 2) = h;
        *(uint32_t*)(sm + OFF_ALO + r1 + col * 2) = l;
    }
}

__device__ __forceinline__ void epi_to_gmem_w(const float* acc,
                                              const float* __restrict__ bias,
                                              bool relu, int row0, int m0, int lane) {
    int g = lane >> 2, tg = lane & 3;
    int ra = row0 + m0 + g;
    int rb = ra + 8;
#pragma unroll
    for (int j = 0; j < 8; j++) {
        int col = j * 8 + tg * 2;
        float b0 = __ldg(bias + col), b1 = __ldg(bias + col + 1);
        float v00 = acc[j * 4 + 0] + b0, v01 = acc[j * 4 + 1] + b1;
        float v10 = acc[j * 4 + 2] + b0, v11 = acc[j * 4 + 3] + b1;
        if (relu) {
            v00 = fmaxf(v00, 0.f); v01 = fmaxf(v01, 0.f);
            v10 = fmaxf(v10, 0.f); v11 = fmaxf(v11, 0.f);
        }
        if (ra < NN) *(float2*)(g_h + (size_t)ra * 64 + col) = make_float2(v00, v01);
        if (rb < NN) *(float2*)(g_h + (size_t)rb * 64 + col) = make_float2(v10, v11);
    }
}

// ================= fused embed MLP =================
__global__ void __launch_bounds__(256, 3) embed_kernel(
    const float* __restrict__ x,
    const float* __restrict__ b1, const float* __restrict__ b2)
{
    extern __shared__ char sm[];
    uint32_t smb = (uint32_t)__cvta_generic_to_shared(sm);
    int lane = threadIdx.x & 31;
    int m0 = (threadIdx.x >> 5) * 16;
    int row0 = blockIdx.x * 128;

    float acc[32];
    zero32(acc);
    stage_A_w(sm, x, row0, DD, 0, m0, lane);
    __syncwarp();
    gemm_unit_w(smb, 0, acc, m0, lane);
    __syncwarp();
    stage_A_w(sm, x, row0, DD, 64, m0, lane);
    __syncwarp();
    gemm_unit_w(smb, 1, acc, m0, lane);
    __syncwarp();
    epi_to_A_w(sm, acc, b1, true, m0, lane);
    __syncwarp();

    zero32(acc);
    gemm_unit_w(smb, 2, acc, m0, lane);
    epi_to_gmem_w(acc, b2, false, row0, m0, lane);
}

// ================= fused conv layer =================
__global__ void __launch_bounds__(256, 3) layer_kernel(
    int t0,
    const float* __restrict__ rb,
    const float* __restrict__ pb1,
    const float* __restrict__ pb2)
{
    extern __shared__ char sm[];
    uint32_t smb = (uint32_t)__cvta_generic_to_shared(sm);
    int lane = threadIdx.x & 31;
    int m0 = (threadIdx.x >> 5) * 16;
    int row0 = blockIdx.x * 128;

    float acc[32];
    zero32(acc);
    stage_A_w(sm, g_agg, row0, HH, 0, m0, lane);
    __syncwarp();
    gemm_unit_w(smb, t0 + 0, acc, m0, lane);     // agg @ rel
    __syncwarp();
    stage_A_w(sm, g_h, row0, HH, 0, m0, lane);
    __syncwarp();
    gemm_unit_w(smb, t0 + 1, acc, m0, lane);     // += h @ root
    __syncwarp();
    epi_to_A_w(sm, acc, rb, false, m0, lane);    // h2
    __syncwarp();

    zero32(acc);
    gemm_unit_w(smb, t0 + 2, acc, m0, lane);     // h2 @ pw1
    __syncwarp();
    epi_to_A_w(sm, acc, pb1, true, m0, lane);    // t
    __syncwarp();

    zero32(acc);
    gemm_unit_w(smb, t0 + 3, acc, m0, lane);     // t @ pw2
    epi_to_gmem_w(acc, pb2, true, row0, m0, lane);
}

// ================= pooling + classifier (proven) =================
__device__ __forceinline__ int lbound(const int* a, int n, int v) {
    int lo = 0, hi = n;
    while (lo < hi) {
        int m = (lo + hi) >> 1;
        if (a[m] < v) lo = m + 1; else hi = m;
    }
    return lo;
}

__global__ void __launch_bounds__(256) pool_kernel(const int* __restrict__ batch) {
    __shared__ int s_lo, s_hi;
    __shared__ float sm[4][64];
    int g = blockIdx.x;
    int tid = threadIdx.x;
    if (tid == 0) {
        s_lo = lbound(batch, NN, g);
        s_hi = lbound(batch, NN, g + 1);
    }
    __syncthreads();
    int lo = s_lo, hi = s_hi;
    int col = tid & 63;
    int rg = tid >> 6;

    float acc = 0.f;
    for (int n = lo + rg; n < hi; n += 4)
        acc += g_h[(size_t)n * HH + col];
    sm[rg][col] = acc;
    __syncthreads();
    if (rg == 0) {
        float s = sm[0][col] + sm[1][col] + sm[2][col] + sm[3][col];
        float inv = 1.0f / fmaxf((float)(hi - lo), 1.0f);
        g_pooled[(size_t)g * HH + col] = s * inv;
    }
}

__global__ void cls_kernel(const float* __restrict__ W,
                           const float* __restrict__ b,
                           float* __restrict__ out)
{
    int tid = blockIdx.x * blockDim.x + threadIdx.x;
    if (tid >= GG * CC) return;
    int g = tid / CC;
    int c = tid % CC;
    float s = b[c];
#pragma unroll
    for (int k = 0; k < HH; k++)
        s += g_pooled[g * HH + k] * W[k * CC + c];
    out[tid] = s;
}

// ================= launcher =================
extern "C" void kernel_launch(void* const* d_in, const int* in_sizes, int n_in,
                              void* d_out, int out_size) {
    const float* x       = (const float*)d_in[0];
    const int*   ei      = (const int*)d_in[1];
    const int*   batch   = (const int*)d_in[2];
    const float* emb_w1  = (const float*)d_in[3];
    const float* emb_b1  = (const float*)d_in[4];
    const float* emb_w2  = (const float*)d_in[5];
    const float* emb_b2  = (const float*)d_in[6];
    const float* rel_w   = (const float*)d_in[7];
    const float* rel_b   = (const float*)d_in[8];
    const float* root_w  = (const float*)d_in[9];
    const float* post_w1 = (const float*)d_in[10];
    const float* post_b1 = (const float*)d_in[11];
    const float* post_w2 = (const float*)d_in[12];
    const float* post_b2 = (const float*)d_in[13];
    const float* cls_w   = (const float*)d_in[14];
    const float* cls_b   = (const float*)d_in[15];
    float*       out     = (float*)d_out;

    const int TB = 256;
    cudaFuncSetAttribute(embed_kernel, cudaFuncAttributeMaxDynamicSharedMemorySize, A_SMEM);
    cudaFuncSetAttribute(layer_kernel, cudaFuncAttributeMaxDynamicSharedMemorySize, A_SMEM);

    // ---- weight fragment prep + bucket build ----
    prep_wfrag_kernel<<<NT_W, 256>>>(emb_w1, emb_w2, rel_w, root_w, post_w1, post_w2);
    zero_cnt_kernel<<<(NN + TB - 1) / TB, TB>>>();
    fill_bucket_kernel<<<(EE + TB - 1) / TB, TB>>>(ei);

    // ---- embed (capture slot 3 -> profiled) ----
    embed_kernel<<<TILES128, 256, A_SMEM>>>(x, emb_b1, emb_b2);

    for (int l = 0; l < LL; l++) {
        agg_kernel<<<(NN * 32 + TB - 1) / TB, TB>>>();
        layer_kernel<<<TILES128, 256, A_SMEM>>>(
            3 + 4 * l,
            rel_b   + (size_t)l * HH,
            post_b1 + (size_t)l * HH,
            post_b2 + (size_t)l * HH);
    }

    // ---- mean pool + classifier ----
    pool_kernel<<<GG, 256>>>(batch);
    cls_kernel<<<(GG * CC + TB - 1) / TB, TB>>>(cls_w, cls_b, out);
}

// round 15
// speedup vs baseline: 1.1995x; 1.0456x over previous
#include <cuda_runtime.h>
#include <cuda_bf16.h>
#include <cstdint>
#include <cstddef>

#define NN 50000
#define EE 1250000
#define HH 64
#define DD 128
#define GG 128
#define CC 10
#define LL 2
#define TILES128 391      // ceil(NN/128)
#define SAB 144           // A row stride in bytes (9 x 16B -> LDSM conflict-free)
#define BK 128            // bucket capacity per node
#define NT_W 11           // weight tiles

// SMEM: single A plane (bf16)
#define A_SMEM (128 * SAB)   // 18,432 B

// ---------------- scratch (static __device__, no allocation) ----------------
__device__ __align__(16) float g_h[NN * HH];
__device__ __align__(16) float g_agg[NN * HH];
__device__ __align__(16) float g_pooled[GG * HH];
__device__ __align__(16) uint4 g_wfrag[NT_W * 1024];   // fragment-ordered weights

__device__ int g_cnt[NN];
__device__ int g_bucket[(size_t)NN * BK];

// ================= bf16 helpers =================
__device__ __forceinline__ void split2(float a, float b, uint32_t& hi, uint32_t& lo) {
    __nv_bfloat16 ha = __float2bfloat16(a), hb = __float2bfloat16(b);
    float ra = a - __bfloat162float(ha);
    float rb = b - __bfloat162float(hb);
    __nv_bfloat16 la = __float2bfloat16(ra), lb = __float2bfloat16(rb);
    hi = (uint32_t)__bfloat16_as_ushort(ha) | ((uint32_t)__bfloat16_as_ushort(hb) << 16);
    lo = (uint32_t)__bfloat16_as_ushort(la) | ((uint32_t)__bfloat16_as_ushort(lb) << 16);
}

__device__ __forceinline__ uint32_t pack_bf2(float a, float b) {
    __nv_bfloat162 t = __floats2bfloat162_rn(a, b);   // a -> low, b -> high
    return *(uint32_t*)&t;
}

// ================= weight fragment prep (once per launch; hi+lo split) =====
// tile t: item = p*256 + ks*64 + plane*32 + lane (uint4 each)
// reg r: n = p*16 + (r>=2 ? 8:0) + lane/4 ; k = ks*16 + (lane%4)*2 + (r&1 ? 8:0)
__global__ void __launch_bounds__(256) prep_wfrag_kernel(
    const float* __restrict__ emb_w1, const float* __restrict__ emb_w2,
    const float* __restrict__ rel_w,  const float* __restrict__ root_w,
    const float* __restrict__ pw1,    const float* __restrict__ pw2)
{
    int t = blockIdx.x;
    const float* W;
    int kbase = 0;
    if (t == 0)      { W = emb_w1; kbase = 0;  }
    else if (t == 1) { W = emb_w1; kbase = 64; }
    else if (t == 2) { W = emb_w2; }
    else {
        int l = (t - 3) >> 2;
        int w = (t - 3) & 3;
        size_t ofs = (size_t)l * HH * HH;
        W = (w == 0) ? rel_w + ofs : (w == 1) ? root_w + ofs
          : (w == 2) ? pw1 + ofs : pw2 + ofs;
    }
    for (int item = threadIdx.x; item < 1024; item += 256) {
        int lane  = item & 31;
        int plane = (item >> 5) & 1;
        int ks    = (item >> 6) & 3;
        int p     = (item >> 8) & 3;
        uint32_t vals[4];
#pragma unroll
        for (int r = 0; r < 4; r++) {
            int n = p * 16 + ((r >> 1) ? 8 : 0) + (lane >> 2);
            int k = ks * 16 + ((lane & 3) << 1) + ((r & 1) ? 8 : 0);
            float a = W[(size_t)(kbase + k) * 64 + n];
            float b = W[(size_t)(kbase + k + 1) * 64 + n];
            uint32_t hi, lo;
            split2(a, b, hi, lo);
            vals[r] = plane ? lo : hi;
        }
        g_wfrag[t * 1024 + item] = make_uint4(vals[0], vals[1], vals[2], vals[3]);
    }
}

// ================= bucket build =================
__global__ void zero_cnt_kernel() {
    int i = blockIdx.x * blockDim.x + threadIdx.x;
    if (i < NN) g_cnt[i] = 0;
}
__global__ void fill_bucket_kernel(const int* __restrict__ ei) {
    int e = blockIdx.x * blockDim.x + threadIdx.x;
    if (e >= EE) return;
    int s = ei[e];
    int d = ei[EE + e];
    int pos = atomicAdd(&g_cnt[d], 1);
    if (pos < BK) g_bucket[((size_t)d << 7) + pos] = s;
}

// ================= aggregation (R12 fp32, proven) =================
__global__ void __launch_bounds__(256) agg_kernel() {
    int wid = (blockIdx.x * blockDim.x + threadIdx.x) >> 5;
    if (wid >= NN) return;
    int lane = threadIdx.x & 31;
    int half = lane >> 4;
    int l16 = lane & 15;

    int deg = g_cnt[wid];
    int n = (deg < BK) ? deg : BK;
    const int* bkt = g_bucket + ((size_t)wid << 7);

    float4 acc = make_float4(0.f, 0.f, 0.f, 0.f);
    for (int e = half; e < n; e += 2) {
        int s = bkt[e];
        float4 v = *(const float4*)(g_h + (size_t)s * HH + (l16 << 2));
        acc.x += v.x; acc.y += v.y; acc.z += v.z; acc.w += v.w;
    }
    acc.x += __shfl_down_sync(0xffffffffu, acc.x, 16);
    acc.y += __shfl_down_sync(0xffffffffu, acc.y, 16);
    acc.z += __shfl_down_sync(0xffffffffu, acc.z, 16);
    acc.w += __shfl_down_sync(0xffffffffu, acc.w, 16);

    if (half == 0) {
        float inv = 1.0f / fmaxf((float)deg, 1.0f);
        acc.x *= inv; acc.y *= inv; acc.z *= inv; acc.w *= inv;
        *(float4*)(g_agg + (size_t)wid * HH + (l16 << 2)) = acc;
    }
}

// ================= MMA + LDSM =================
__device__ __forceinline__ void mma_bf16(float* acc,
                                         uint32_t a0, uint32_t a1, uint32_t a2, uint32_t a3,
                                         uint32_t b0, uint32_t b1) {
    asm volatile(
        "mma.sync.aligned.m16n8k16.row.col.f32.bf16.bf16.f32 "
        "{%0,%1,%2,%3}, {%4,%5,%6,%7}, {%8,%9}, {%0,%1,%2,%3};"
        : "+f"(acc[0]), "+f"(acc[1]), "+f"(acc[2]), "+f"(acc[3])
        : "r"(a0), "r"(a1), "r"(a2), "r"(a3), "r"(b0), "r"(b1));
}

__device__ __forceinline__ void ldsm4(uint32_t addr,
                                      uint32_t& r0, uint32_t& r1,
                                      uint32_t& r2, uint32_t& r3) {
    asm volatile("ldmatrix.sync.aligned.m8n8.x4.shared.b16 {%0,%1,%2,%3}, [%4];"
                 : "=r"(r0), "=r"(r1), "=r"(r2), "=r"(r3) : "r"(addr));
}

// ================= A staging: single bf16 plane =================
__device__ __forceinline__ void stage_A_w(char* sm, const float* __restrict__ A,
                                          int row0, int K, int kofs,
                                          int m0, int lane) {
    int r = m0 + (lane & 15);
    int cb = (lane >> 4) << 5;
    int row = row0 + r;
#pragma unroll
    for (int cc = 0; cc < 2; cc++) {
        int c0 = cb + cc * 16;
        float v[16];
        if (row < NN) {
            const float* src = A + (size_t)row * K + kofs + c0;
#pragma unroll
            for (int q = 0; q < 4; q++) {
                float4 f = *(const float4*)(src + q * 4);
                v[q * 4 + 0] = f.x; v[q * 4 + 1] = f.y;
                v[q * 4 + 2] = f.z; v[q * 4 + 3] = f.w;
            }
        } else {
#pragma unroll
            for (int q = 0; q < 16; q++) v[q] = 0.f;
        }
        uint4 h0;
        h0.x = pack_bf2(v[0],  v[1]);  h0.y = pack_bf2(v[2],  v[3]);
        h0.z = pack_bf2(v[4],  v[5]);  h0.w = pack_bf2(v[6],  v[7]);
        uint4 h1;
        h1.x = pack_bf2(v[8],  v[9]);  h1.y = pack_bf2(v[10], v[11]);
        h1.z = pack_bf2(v[12], v[13]); h1.w = pack_bf2(v[14], v[15]);
        char* ph = sm + (size_t)r * SAB + c0 * 2;
        ((uint4*)ph)[0] = h0; ((uint4*)ph)[1] = h1;
    }
}

// ================= GEMM unit: A (1 plane, LDSM), B hi+lo from g_wfrag ======
__device__ __forceinline__ void gemm_unit_w(uint32_t smb, int t,
                                            float* acc, int m0, int lane) {
    const uint4* wf = g_wfrag + t * 1024 + lane;
    uint32_t a_addr = smb + (uint32_t)((m0 + (lane & 15)) * SAB + ((lane >> 4) << 4));

#pragma unroll
    for (int ks = 0; ks < 4; ks++) {
        uint32_t a0, a1, a2, a3;
        ldsm4(a_addr + ks * 32, a0, a1, a2, a3);
#pragma unroll
        for (int p = 0; p < 4; p++) {
            uint4 bh = wf[(p * 4 + ks) * 64];        // hi plane
            uint4 bl = wf[(p * 4 + ks) * 64 + 32];   // lo plane
            float* A0 = acc + (2 * p) * 4;
            float* A1 = acc + (2 * p + 1) * 4;
            mma_bf16(A0, a0, a1, a2, a3, bh.x, bh.y);
            mma_bf16(A1, a0, a1, a2, a3, bh.z, bh.w);
            mma_bf16(A0, a0, a1, a2, a3, bl.x, bl.y);
            mma_bf16(A1, a0, a1, a2, a3, bl.z, bl.w);
        }
    }
}

__device__ __forceinline__ void zero32(float* a) {
#pragma unroll
    for (int i = 0; i < 32; i++) a[i] = 0.f;
}

// epilogue -> single bf16 A plane in smem
__device__ __forceinline__ void epi_to_A_w(char* sm, const float* acc,
                                           const float* __restrict__ bias,
                                           bool relu, int m0, int lane) {
    int g = lane >> 2, tg = lane & 3;
    size_t r0 = (size_t)(m0 + g) * SAB;
    size_t r1 = (size_t)(m0 + g + 8) * SAB;
#pragma unroll
    for (int j = 0; j < 8; j++) {
        int col = j * 8 + tg * 2;
        float b0 = __ldg(bias + col), b1 = __ldg(bias + col + 1);
        float v00 = acc[j * 4 + 0] + b0, v01 = acc[j * 4 + 1] + b1;
        float v10 = acc[j * 4 + 2] + b0, v11 = acc[j * 4 + 3] + b1;
        if (relu) {
            v00 = fmaxf(v00, 0.f); v01 = fmaxf(v01, 0.f);
            v10 = fmaxf(v10, 0.f); v11 = fmaxf(v11, 0.f);
        }
        *(uint32_t*)(sm + r0 + col * 2) = pack_bf2(v00, v01);
        *(uint32_t*)(sm + r1 + col * 2) = pack_bf2(v10, v11);
    }
}

__device__ __forceinline__ void epi_to_gmem_w(const float* acc,
                                              const float* __restrict__ bias,
                                              bool relu, int row0, int m0, int lane) {
    int g = lane >> 2, tg = lane & 3;
    int ra = row0 + m0 + g;
    int rb = ra + 8;
#pragma unroll
    for (int j = 0; j < 8; j++) {
        int col = j * 8 + tg * 2;
        float b0 = __ldg(bias + col), b1 = __ldg(bias + col + 1);
        float v00 = acc[j * 4 + 0] + b0, v01 = acc[j * 4 + 1] + b1;
        float v10 = acc[j * 4 + 2] + b0, v11 = acc[j * 4 + 3] + b1;
        if (relu) {
            v00 = fmaxf(v00, 0.f); v01 = fmaxf(v01, 0.f);
            v10 = fmaxf(v10, 0.f); v11 = fmaxf(v11, 0.f);
        }
        if (ra < NN) *(float2*)(g_h + (size_t)ra * 64 + col) = make_float2(v00, v01);
        if (rb < NN) *(float2*)(g_h + (size_t)rb * 64 + col) = make_float2(v10, v11);
    }
}

// ================= fused embed MLP =================
__global__ void __launch_bounds__(256, 3) embed_kernel(
    const float* __restrict__ x,
    const float* __restrict__ b1, const float* __restrict__ b2)
{
    extern __shared__ char sm[];
    uint32_t smb = (uint32_t)__cvta_generic_to_shared(sm);
    int lane = threadIdx.x & 31;
    int m0 = (threadIdx.x >> 5) * 16;
    int row0 = blockIdx.x * 128;

    float acc[32];
    zero32(acc);
    stage_A_w(sm, x, row0, DD, 0, m0, lane);
    __syncwarp();
    gemm_unit_w(smb, 0, acc, m0, lane);
    __syncwarp();
    stage_A_w(sm, x, row0, DD, 64, m0, lane);
    __syncwarp();
    gemm_unit_w(smb, 1, acc, m0, lane);
    __syncwarp();
    epi_to_A_w(sm, acc, b1, true, m0, lane);
    __syncwarp();

    zero32(acc);
    gemm_unit_w(smb, 2, acc, m0, lane);
    epi_to_gmem_w(acc, b2, false, row0, m0, lane);
}

// ================= fused conv layer =================
__global__ void __launch_bounds__(256, 3) layer_kernel(
    int t0,
    const float* __restrict__ rb,
    const float* __restrict__ pb1,
    const float* __restrict__ pb2)
{
    extern __shared__ char sm[];
    uint32_t smb = (uint32_t)__cvta_generic_to_shared(sm);
    int lane = threadIdx.x & 31;
    int m0 = (threadIdx.x >> 5) * 16;
    int row0 = blockIdx.x * 128;

    float acc[32];
    zero32(acc);
    stage_A_w(sm, g_agg, row0, HH, 0, m0, lane);
    __syncwarp();
    gemm_unit_w(smb, t0 + 0, acc, m0, lane);     // agg @ rel
    __syncwarp();
    stage_A_w(sm, g_h, row0, HH, 0, m0, lane);
    __syncwarp();
    gemm_unit_w(smb, t0 + 1, acc, m0, lane);     // += h @ root
    __syncwarp();
    epi_to_A_w(sm, acc, rb, false, m0, lane);    // h2
    __syncwarp();

    zero32(acc);
    gemm_unit_w(smb, t0 + 2, acc, m0, lane);     // h2 @ pw1
    __syncwarp();
    epi_to_A_w(sm, acc, pb1, true, m0, lane);    // t
    __syncwarp();

    zero32(acc);
    gemm_unit_w(smb, t0 + 3, acc, m0, lane);     // t @ pw2
    epi_to_gmem_w(acc, pb2, true, row0, m0, lane);
}

// ================= pooling + classifier (proven) =================
__device__ __forceinline__ int lbound(const int* a, int n, int v) {
    int lo = 0, hi = n;
    while (lo < hi) {
        int m = (lo + hi) >> 1;
        if (a[m] < v) lo = m + 1; else hi = m;
    }
    return lo;
}

__global__ void __launch_bounds__(256) pool_kernel(const int* __restrict__ batch) {
    __shared__ int s_lo, s_hi;
    __shared__ float sm[4][64];
    int g = blockIdx.x;
    int tid = threadIdx.x;
    if (tid == 0) {
        s_lo = lbound(batch, NN, g);
        s_hi = lbound(batch, NN, g + 1);
    }
    __syncthreads();
    int lo = s_lo, hi = s_hi;
    int col = tid & 63;
    int rg = tid >> 6;

    float acc = 0.f;
    for (int n = lo + rg; n < hi; n += 4)
        acc += g_h[(size_t)n * HH + col];
    sm[rg][col] = acc;
    __syncthreads();
    if (rg == 0) {
        float s = sm[0][col] + sm[1][col] + sm[2][col] + sm[3][col];
        float inv = 1.0f / fmaxf((float)(hi - lo), 1.0f);
        g_pooled[(size_t)g * HH + col] = s * inv;
    }
}

__global__ void cls_kernel(const float* __restrict__ W,
                           const float* __restrict__ b,
                           float* __restrict__ out)
{
    int tid = blockIdx.x * blockDim.x + threadIdx.x;
    if (tid >= GG * CC) return;
    int g = tid / CC;
    int c = tid % CC;
    float s = b[c];
#pragma unroll
    for (int k = 0; k < HH; k++)
        s += g_pooled[g * HH + k] * W[k * CC + c];
    out[tid] = s;
}

// ================= launcher =================
extern "C" void kernel_launch(void* const* d_in, const int* in_sizes, int n_in,
                              void* d_out, int out_size) {
    const float* x       = (const float*)d_in[0];
    const int*   ei      = (const int*)d_in[1];
    const int*   batch   = (const int*)d_in[2];
    const float* emb_w1  = (const float*)d_in[3];
    const float* emb_b1  = (const float*)d_in[4];
    const float* emb_w2  = (const float*)d_in[5];
    const float* emb_b2  = (const float*)d_in[6];
    const float* rel_w   = (const float*)d_in[7];
    const float* rel_b   = (const float*)d_in[8];
    const float* root_w  = (const float*)d_in[9];
    const float* post_w1 = (const float*)d_in[10];
    const float* post_b1 = (const float*)d_in[11];
    const float* post_w2 = (const float*)d_in[12];
    const float* post_b2 = (const float*)d_in[13];
    const float* cls_w   = (const float*)d_in[14];
    const float* cls_b   = (const float*)d_in[15];
    float*       out     = (float*)d_out;

    const int TB = 256;
    cudaFuncSetAttribute(embed_kernel, cudaFuncAttributeMaxDynamicSharedMemorySize, A_SMEM);
    cudaFuncSetAttribute(layer_kernel, cudaFuncAttributeMaxDynamicSharedMemorySize, A_SMEM);

    // ---- weight fragment prep + bucket build ----
    prep_wfrag_kernel<<<NT_W, 256>>>(emb_w1, emb_w2, rel_w, root_w, post_w1, post_w2);
    zero_cnt_kernel<<<(NN + TB - 1) / TB, TB>>>();
    fill_bucket_kernel<<<(EE + TB - 1) / TB, TB>>>(ei);

    // ---- embed (capture slot 3 -> profiled) ----
    embed_kernel<<<TILES128, 256, A_SMEM>>>(x, emb_b1, emb_b2);

    for (int l = 0; l < LL; l++) {
        agg_kernel<<<(NN * 32 + TB - 1) / TB, TB>>>();
        layer_kernel<<<TILES128, 256, A_SMEM>>>(
            3 + 4 * l,
            rel_b   + (size_t)l * HH,
            post_b1 + (size_t)l * HH,
            post_b2 + (size_t)l * HH);
    }

    // ---- mean pool + classifier ----
    pool_kernel<<<GG, 256>>>(batch);
    cls_kernel<<<(GG * CC + TB - 1) / TB, TB>>>(cls_w, cls_b, out);
}

// round 16
// speedup vs baseline: 1.3001x; 1.0839x over previous
#include <cuda_runtime.h>
#include <cuda_bf16.h>
#include <cuda_fp16.h>
#include <cstdint>
#include <cstddef>

#define NN 50000
#define EE 1250000
#define HH 64
#define DD 128
#define GG 128
#define CC 10
#define LL 2
#define TILES128 391      // ceil(NN/128)
#define SAB 144           // A row stride in bytes (9 x 16B -> LDSM conflict-free)
#define BK 128            // bucket capacity per node
#define NT_W 11           // weight tiles

// SMEM: two A planes (bf16)
#define PLANE   (128 * SAB)       // 18,432 B
#define A_SMEM  (2 * PLANE)       // 36,864 B

// ---------------- scratch (static __device__, no allocation) ----------------
__device__ __align__(16) __half g_h[NN * HH];    // node features, fp16 ONLY
__device__ __align__(16) float  g_agg[NN * HH];  // aggregated mean (fp32)
__device__ __align__(16) float  g_pooled[GG * HH];
__device__ __align__(16) uint4  g_wfrag[NT_W * 1024];

__device__ int g_cnt[NN];
__device__ int g_bucket[(size_t)NN * BK];

// ================= bf16 helpers =================
__device__ __forceinline__ void split2(float a, float b, uint32_t& hi, uint32_t& lo) {
    __nv_bfloat16 ha = __float2bfloat16(a), hb = __float2bfloat16(b);
    float ra = a - __bfloat162float(ha);
    float rb = b - __bfloat162float(hb);
    __nv_bfloat16 la = __float2bfloat16(ra), lb = __float2bfloat16(rb);
    hi = (uint32_t)__bfloat16_as_ushort(ha) | ((uint32_t)__bfloat16_as_ushort(hb) << 16);
    lo = (uint32_t)__bfloat16_as_ushort(la) | ((uint32_t)__bfloat16_as_ushort(lb) << 16);
}

__device__ __forceinline__ uint32_t pack_bf2(float a, float b) {
    __nv_bfloat162 t = __floats2bfloat162_rn(a, b);
    return *(uint32_t*)&t;
}

__device__ __forceinline__ uint32_t h2_to_bf2(uint32_t h2) {
    float2 f = __half22float2(*(__half2*)&h2);
    return pack_bf2(f.x, f.y);
}

// ================= weight fragment prep (hi+lo split, proven) =============
__global__ void __launch_bounds__(256) prep_wfrag_kernel(
    const float* __restrict__ emb_w1, const float* __restrict__ emb_w2,
    const float* __restrict__ rel_w,  const float* __restrict__ root_w,
    const float* __restrict__ pw1,    const float* __restrict__ pw2)
{
    int t = blockIdx.x;
    const float* W;
    int kbase = 0;
    if (t == 0)      { W = emb_w1; kbase = 0;  }
    else if (t == 1) { W = emb_w1; kbase = 64; }
    else if (t == 2) { W = emb_w2; }
    else {
        int l = (t - 3) >> 2;
        int w = (t - 3) & 3;
        size_t ofs = (size_t)l * HH * HH;
        W = (w == 0) ? rel_w + ofs : (w == 1) ? root_w + ofs
          : (w == 2) ? pw1 + ofs : pw2 + ofs;
    }
    for (int item = threadIdx.x; item < 1024; item += 256) {
        int lane  = item & 31;
        int plane = (item >> 5) & 1;
        int ks    = (item >> 6) & 3;
        int p     = (item >> 8) & 3;
        uint32_t vals[4];
#pragma unroll
        for (int r = 0; r < 4; r++) {
            int n = p * 16 + ((r >> 1) ? 8 : 0) + (lane >> 2);
            int k = ks * 16 + ((lane & 3) << 1) + ((r & 1) ? 8 : 0);
            float a = W[(size_t)(kbase + k) * 64 + n];
            float b = W[(size_t)(kbase + k + 1) * 64 + n];
            uint32_t hi, lo;
            split2(a, b, hi, lo);
            vals[r] = plane ? lo : hi;
        }
        g_wfrag[t * 1024 + item] = make_uint4(vals[0], vals[1], vals[2], vals[3]);
    }
}

// ================= bucket build =================
__global__ void zero_cnt_kernel() {
    int i = blockIdx.x * blockDim.x + threadIdx.x;
    if (i < NN) g_cnt[i] = 0;
}
__global__ void fill_bucket_kernel(const int* __restrict__ ei) {
    int e = blockIdx.x * blockDim.x + threadIdx.x;
    if (e >= EE) return;
    int s = ei[e];
    int d = ei[EE + e];
    int pos = atomicAdd(&g_cnt[d], 1);
    if (pos < BK) g_bucket[((size_t)d << 7) + pos] = s;
}

// ================= aggregation: fp16 gather, fp32 accumulate ===============
__global__ void __launch_bounds__(256) agg_kernel() {
    int wid = (blockIdx.x * blockDim.x + threadIdx.x) >> 5;
    if (wid >= NN) return;
    int lane = threadIdx.x & 31;
    int half = lane >> 4;
    int l16 = lane & 15;

    int deg = g_cnt[wid];
    int n = (deg < BK) ? deg : BK;
    const int* bkt = g_bucket + ((size_t)wid << 7);

    float4 acc = make_float4(0.f, 0.f, 0.f, 0.f);
    for (int e = half; e < n; e += 2) {
        int s = bkt[e];
        uint2 u = *(const uint2*)(g_h + (size_t)s * HH + (l16 << 2));
        float2 f0 = __half22float2(*(const __half2*)&u.x);
        float2 f1 = __half22float2(*(const __half2*)&u.y);
        acc.x += f0.x; acc.y += f0.y; acc.z += f1.x; acc.w += f1.y;
    }
    acc.x += __shfl_down_sync(0xffffffffu, acc.x, 16);
    acc.y += __shfl_down_sync(0xffffffffu, acc.y, 16);
    acc.z += __shfl_down_sync(0xffffffffu, acc.z, 16);
    acc.w += __shfl_down_sync(0xffffffffu, acc.w, 16);

    if (half == 0) {
        float inv = 1.0f / fmaxf((float)deg, 1.0f);
        acc.x *= inv; acc.y *= inv; acc.z *= inv; acc.w *= inv;
        *(float4*)(g_agg + (size_t)wid * HH + (l16 << 2)) = acc;
    }
}

// ================= MMA + LDSM =================
__device__ __forceinline__ void mma_bf16(float* acc,
                                         uint32_t a0, uint32_t a1, uint32_t a2, uint32_t a3,
                                         uint32_t b0, uint32_t b1) {
    asm volatile(
        "mma.sync.aligned.m16n8k16.row.col.f32.bf16.bf16.f32 "
        "{%0,%1,%2,%3}, {%4,%5,%6,%7}, {%8,%9}, {%0,%1,%2,%3};"
        : "+f"(acc[0]), "+f"(acc[1]), "+f"(acc[2]), "+f"(acc[3])
        : "r"(a0), "r"(a1), "r"(a2), "r"(a3), "r"(b0), "r"(b1));
}

__device__ __forceinline__ void ldsm4(uint32_t addr,
                                      uint32_t& r0, uint32_t& r1,
                                      uint32_t& r2, uint32_t& r3) {
    asm volatile("ldmatrix.sync.aligned.m8n8.x4.shared.b16 {%0,%1,%2,%3}, [%4];"
                 : "=r"(r0), "=r"(r1), "=r"(r2), "=r"(r3) : "r"(addr));
}

// ================= A staging =================
// fp32 source -> bf16 plane
__device__ __forceinline__ void stage_A_f32(char* sm, int plane_off,
                                            const float* __restrict__ A,
                                            int row0, int K, int kofs,
                                            int m0, int lane) {
    int r = m0 + (lane & 15);
    int cb = (lane >> 4) << 5;
    int row = row0 + r;
#pragma unroll
    for (int cc = 0; cc < 2; cc++) {
        int c0 = cb + cc * 16;
        float v[16];
        if (row < NN) {
            const float* src = A + (size_t)row * K + kofs + c0;
#pragma unroll
            for (int q = 0; q < 4; q++) {
                float4 f = *(const float4*)(src + q * 4);
                v[q * 4 + 0] = f.x; v[q * 4 + 1] = f.y;
                v[q * 4 + 2] = f.z; v[q * 4 + 3] = f.w;
            }
        } else {
#pragma unroll
            for (int q = 0; q < 16; q++) v[q] = 0.f;
        }
        uint4 h0, h1;
        h0.x = pack_bf2(v[0],  v[1]);  h0.y = pack_bf2(v[2],  v[3]);
        h0.z = pack_bf2(v[4],  v[5]);  h0.w = pack_bf2(v[6],  v[7]);
        h1.x = pack_bf2(v[8],  v[9]);  h1.y = pack_bf2(v[10], v[11]);
        h1.z = pack_bf2(v[12], v[13]); h1.w = pack_bf2(v[14], v[15]);
        char* ph = sm + plane_off + (size_t)r * SAB + c0 * 2;
        ((uint4*)ph)[0] = h0; ((uint4*)ph)[1] = h1;
    }
}

// fp16 source (g_h) -> bf16 plane; K fixed at 64
__device__ __forceinline__ void stage_A_f16(char* sm, int plane_off,
                                            const __half* __restrict__ A,
                                            int row0, int m0, int lane) {
    int r = m0 + (lane & 15);
    int cb = (lane >> 4) << 5;
    int row = row0 + r;
#pragma unroll
    for (int cc = 0; cc < 2; cc++) {
        int c0 = cb + cc * 16;
        uint4 u = make_uint4(0, 0, 0, 0), u2 = make_uint4(0, 0, 0, 0);
        if (row < NN) {
            const uint4* src = (const uint4*)(A + (size_t)row * HH + c0);
            u = src[0];       // 8 halfs
            u2 = src[1];      // next 8 halfs
        }
        uint4 h0, h1;
        h0.x = h2_to_bf2(u.x);  h0.y = h2_to_bf2(u.y);
        h0.z = h2_to_bf2(u.z);  h0.w = h2_to_bf2(u.w);
        h1.x = h2_to_bf2(u2.x); h1.y = h2_to_bf2(u2.y);
        h1.z = h2_to_bf2(u2.z); h1.w = h2_to_bf2(u2.w);
        char* ph = sm + plane_off + (size_t)r * SAB + c0 * 2;
        ((uint4*)ph)[0] = h0; ((uint4*)ph)[1] = h1;
    }
}

// ================= GEMM unit: A (plane, LDSM), B hi+lo from g_wfrag ========
__device__ __forceinline__ void gemm_unit_w(uint32_t smb, int plane_off, int t,
                                            float* acc, int m0, int lane) {
    const uint4* wf = g_wfrag + t * 1024 + lane;
    uint32_t a_addr = smb + plane_off
                    + (uint32_t)((m0 + (lane & 15)) * SAB + ((lane >> 4) << 4));

#pragma unroll
    for (int ks = 0; ks < 4; ks++) {
        uint32_t a0, a1, a2, a3;
        ldsm4(a_addr + ks * 32, a0, a1, a2, a3);
#pragma unroll
        for (int p = 0; p < 4; p++) {
            uint4 bh = wf[(p * 4 + ks) * 64];
            uint4 bl = wf[(p * 4 + ks) * 64 + 32];
            float* A0 = acc + (2 * p) * 4;
            float* A1 = acc + (2 * p + 1) * 4;
            mma_bf16(A0, a0, a1, a2, a3, bh.x, bh.y);
            mma_bf16(A1, a0, a1, a2, a3, bh.z, bh.w);
            mma_bf16(A0, a0, a1, a2, a3, bl.x, bl.y);
            mma_bf16(A1, a0, a1, a2, a3, bl.z, bl.w);
        }
    }
}

__device__ __forceinline__ void zero32(float* a) {
#pragma unroll
    for (int i = 0; i < 32; i++) a[i] = 0.f;
}

// epilogue -> bf16 plane 0 in smem
__device__ __forceinline__ void epi_to_A_w(char* sm, const float* acc,
                                           const float* __restrict__ bias,
                                           bool relu, int m0, int lane) {
    int g = lane >> 2, tg = lane & 3;
    size_t r0 = (size_t)(m0 + g) * SAB;
    size_t r1 = (size_t)(m0 + g + 8) * SAB;
#pragma unroll
    for (int j = 0; j < 8; j++) {
        int col = j * 8 + tg * 2;
        float b0 = __ldg(bias + col), b1 = __ldg(bias + col + 1);
        float v00 = acc[j * 4 + 0] + b0, v01 = acc[j * 4 + 1] + b1;
        float v10 = acc[j * 4 + 2] + b0, v11 = acc[j * 4 + 3] + b1;
        if (relu) {
            v00 = fmaxf(v00, 0.f); v01 = fmaxf(v01, 0.f);
            v10 = fmaxf(v10, 0.f); v11 = fmaxf(v11, 0.f);
        }
        *(uint32_t*)(sm + r0 + col * 2) = pack_bf2(v00, v01);
        *(uint32_t*)(sm + r1 + col * 2) = pack_bf2(v10, v11);
    }
}

// final epilogue: acc + bias (opt relu) -> fp16 g_h
__device__ __forceinline__ void epi_to_gmem_w(const float* acc,
                                              const float* __restrict__ bias,
                                              bool relu, int row0, int m0, int lane) {
    int g = lane >> 2, tg = lane & 3;
    int ra = row0 + m0 + g;
    int rb = ra + 8;
#pragma unroll
    for (int j = 0; j < 8; j++) {
        int col = j * 8 + tg * 2;
        float b0 = __ldg(bias + col), b1 = __ldg(bias + col + 1);
        float v00 = acc[j * 4 + 0] + b0, v01 = acc[j * 4 + 1] + b1;
        float v10 = acc[j * 4 + 2] + b0, v11 = acc[j * 4 + 3] + b1;
        if (relu) {
            v00 = fmaxf(v00, 0.f); v01 = fmaxf(v01, 0.f);
            v10 = fmaxf(v10, 0.f); v11 = fmaxf(v11, 0.f);
        }
        if (ra < NN)
            *(__half2*)(g_h + (size_t)ra * HH + col) = __floats2half2_rn(v00, v01);
        if (rb < NN)
            *(__half2*)(g_h + (size_t)rb * HH + col) = __floats2half2_rn(v10, v11);
    }
}

// ================= fused embed MLP =================
__global__ void __launch_bounds__(256, 3) embed_kernel(
    const float* __restrict__ x,
    const float* __restrict__ b1, const float* __restrict__ b2)
{
    extern __shared__ char sm[];
    uint32_t smb = (uint32_t)__cvta_generic_to_shared(sm);
    int lane = threadIdx.x & 31;
    int m0 = (threadIdx.x >> 5) * 16;
    int row0 = blockIdx.x * 128;

    // stage BOTH x tiles upfront (4 outstanding LDG.128/thread)
    stage_A_f32(sm, 0,     x, row0, DD, 0,  m0, lane);
    stage_A_f32(sm, PLANE, x, row0, DD, 64, m0, lane);
    __syncwarp();

    float acc[32];
    zero32(acc);
    gemm_unit_w(smb, 0,     0, acc, m0, lane);
    gemm_unit_w(smb, PLANE, 1, acc, m0, lane);
    __syncwarp();
    epi_to_A_w(sm, acc, b1, true, m0, lane);       // t = relu(.+b1) -> plane0
    __syncwarp();

    zero32(acc);
    gemm_unit_w(smb, 0, 2, acc, m0, lane);
    epi_to_gmem_w(acc, b2, false, row0, m0, lane); // h = . + b2 (fp16)
}

// ================= fused conv layer =================
__global__ void __launch_bounds__(256, 3) layer_kernel(
    int t0,
    const float* __restrict__ rb,
    const float* __restrict__ pb1,
    const float* __restrict__ pb2)
{
    extern __shared__ char sm[];
    uint32_t smb = (uint32_t)__cvta_generic_to_shared(sm);
    int lane = threadIdx.x & 31;
    int m0 = (threadIdx.x >> 5) * 16;
    int row0 = blockIdx.x * 128;

    // stage agg (plane0) and h (plane1) upfront
    stage_A_f32(sm, 0, g_agg, row0, HH, 0, m0, lane);
    stage_A_f16(sm, PLANE, g_h, row0, m0, lane);
    __syncwarp();

    float acc[32];
    zero32(acc);
    gemm_unit_w(smb, 0,     t0 + 0, acc, m0, lane);   // agg @ rel
    gemm_unit_w(smb, PLANE, t0 + 1, acc, m0, lane);   // += h @ root
    __syncwarp();
    epi_to_A_w(sm, acc, rb, false, m0, lane);         // h2 -> plane0
    __syncwarp();

    zero32(acc);
    gemm_unit_w(smb, 0, t0 + 2, acc, m0, lane);       // h2 @ pw1
    __syncwarp();
    epi_to_A_w(sm, acc, pb1, true, m0, lane);         // t -> plane0
    __syncwarp();

    zero32(acc);
    gemm_unit_w(smb, 0, t0 + 3, acc, m0, lane);       // t @ pw2
    epi_to_gmem_w(acc, pb2, true, row0, m0, lane);    // h (fp16)
}

// ================= pooling + classifier =================
__device__ __forceinline__ int lbound(const int* a, int n, int v) {
    int lo = 0, hi = n;
    while (lo < hi) {
        int m = (lo + hi) >> 1;
        if (a[m] < v) lo = m + 1; else hi = m;
    }
    return lo;
}

__global__ void __launch_bounds__(256) pool_kernel(const int* __restrict__ batch) {
    __shared__ int s_lo, s_hi;
    __shared__ float sm[4][64];
    int g = blockIdx.x;
    int tid = threadIdx.x;
    if (tid == 0) {
        s_lo = lbound(batch, NN, g);
        s_hi = lbound(batch, NN, g + 1);
    }
    __syncthreads();
    int lo = s_lo, hi = s_hi;
    int col = tid & 63;
    int rg = tid >> 6;

    float acc = 0.f;
    for (int n = lo + rg; n < hi; n += 4)
        acc += __half2float(g_h[(size_t)n * HH + col]);
    sm[rg][col] = acc;
    __syncthreads();
    if (rg == 0) {
        float s = sm[0][col] + sm[1][col] + sm[2][col] + sm[3][col];
        float inv = 1.0f / fmaxf((float)(hi - lo), 1.0f);
        g_pooled[(size_t)g * HH + col] = s * inv;
    }
}

__global__ void cls_kernel(const float* __restrict__ W,
                           const float* __restrict__ b,
                           float* __restrict__ out)
{
    int tid = blockIdx.x * blockDim.x + threadIdx.x;
    if (tid >= GG * CC) return;
    int g = tid / CC;
    int c = tid % CC;
    float s = b[c];
#pragma unroll
    for (int k = 0; k < HH; k++)
        s += g_pooled[g * HH + k] * W[k * CC + c];
    out[tid] = s;
}

// ================= launcher =================
extern "C" void kernel_launch(void* const* d_in, const int* in_sizes, int n_in,
                              void* d_out, int out_size) {
    const float* x       = (const float*)d_in[0];
    const int*   ei      = (const int*)d_in[1];
    const int*   batch   = (const int*)d_in[2];
    const float* emb_w1  = (const float*)d_in[3];
    const float* emb_b1  = (const float*)d_in[4];
    const float* emb_w2  = (const float*)d_in[5];
    const float* emb_b2  = (const float*)d_in[6];
    const float* rel_w   = (const float*)d_in[7];
    const float* rel_b   = (const float*)d_in[8];
    const float* root_w  = (const float*)d_in[9];
    const float* post_w1 = (const float*)d_in[10];
    const float* post_b1 = (const float*)d_in[11];
    const float* post_w2 = (const float*)d_in[12];
    const float* post_b2 = (const float*)d_in[13];
    const float* cls_w   = (const float*)d_in[14];
    const float* cls_b   = (const float*)d_in[15];
    float*       out     = (float*)d_out;

    const int TB = 256;
    cudaFuncSetAttribute(embed_kernel, cudaFuncAttributeMaxDynamicSharedMemorySize, A_SMEM);
    cudaFuncSetAttribute(layer_kernel, cudaFuncAttributeMaxDynamicSharedMemorySize, A_SMEM);

    // ---- weight fragment prep + bucket build ----
    prep_wfrag_kernel<<<NT_W, 256>>>(emb_w1, emb_w2, rel_w, root_w, post_w1, post_w2);
    zero_cnt_kernel<<<(NN + TB - 1) / TB, TB>>>();
    fill_bucket_kernel<<<(EE + TB - 1) / TB, TB>>>(ei);

    // ---- embed (capture slot 3 -> profiled) ----
    embed_kernel<<<TILES128, 256, A_SMEM>>>(x, emb_b1, emb_b2);

    for (int l = 0; l < LL; l++) {
        agg_kernel<<<(NN * 32 + TB - 1) / TB, TB>>>();
        layer_kernel<<<TILES128, 256, A_SMEM>>>(
            3 + 4 * l,
            rel_b   + (size_t)l * HH,
            post_b1 + (size_t)l * HH,
            post_b2 + (size_t)l * HH);
    }

    // ---- mean pool + classifier ----
    pool_kernel<<<GG, 256>>>(batch);
    cls_kernel<<<(GG * CC + TB - 1) / TB, TB>>>(cls_w, cls_b, out);
}

// round 17
// speedup vs baseline: 1.3744x; 1.0571x over previous
#include <cuda_runtime.h>
#include <cuda_bf16.h>
#include <cuda_fp16.h>
#include <cstdint>
#include <cstddef>

#define NN 50000
#define EE 1250000
#define HH 64
#define DD 128
#define GG 128
#define CC 10
#define LL 2
#define TILES128 391      // ceil(NN/128)
#define SAB 144           // A row stride in bytes (9 x 16B -> LDSM conflict-free)
#define BK 128            // bucket capacity per node
#define NT_W 11           // weight tiles

// SMEM: two A planes (bf16)
#define PLANE   (128 * SAB)       // 18,432 B
#define A_SMEM  (2 * PLANE)       // 36,864 B

// ---------------- scratch (static __device__, no allocation) ----------------
__device__ __align__(16) __half g_h[NN * HH];    // node features, fp16
__device__ __align__(16) __half g_agg[NN * HH];  // aggregated mean, fp16
__device__ __align__(16) float  g_pooled[GG * HH];
__device__ __align__(16) uint4  g_wfrag[NT_W * 1024];

__device__ int g_cnt[NN];
__device__ int g_bucket[(size_t)NN * BK];

// ================= bf16 helpers =================
__device__ __forceinline__ void split2(float a, float b, uint32_t& hi, uint32_t& lo) {
    __nv_bfloat16 ha = __float2bfloat16(a), hb = __float2bfloat16(b);
    float ra = a - __bfloat162float(ha);
    float rb = b - __bfloat162float(hb);
    __nv_bfloat16 la = __float2bfloat16(ra), lb = __float2bfloat16(rb);
    hi = (uint32_t)__bfloat16_as_ushort(ha) | ((uint32_t)__bfloat16_as_ushort(hb) << 16);
    lo = (uint32_t)__bfloat16_as_ushort(la) | ((uint32_t)__bfloat16_as_ushort(lb) << 16);
}

__device__ __forceinline__ uint32_t pack_bf2(float a, float b) {
    __nv_bfloat162 t = __floats2bfloat162_rn(a, b);
    return *(uint32_t*)&t;
}

__device__ __forceinline__ uint32_t h2_to_bf2(uint32_t h2) {
    float2 f = __half22float2(*(__half2*)&h2);
    return pack_bf2(f.x, f.y);
}

// ================= weight fragment prep (hi+lo split, proven) =============
__global__ void __launch_bounds__(256) prep_wfrag_kernel(
    const float* __restrict__ emb_w1, const float* __restrict__ emb_w2,
    const float* __restrict__ rel_w,  const float* __restrict__ root_w,
    const float* __restrict__ pw1,    const float* __restrict__ pw2)
{
    int t = blockIdx.x;
    const float* W;
    int kbase = 0;
    if (t == 0)      { W = emb_w1; kbase = 0;  }
    else if (t == 1) { W = emb_w1; kbase = 64; }
    else if (t == 2) { W = emb_w2; }
    else {
        int l = (t - 3) >> 2;
        int w = (t - 3) & 3;
        size_t ofs = (size_t)l * HH * HH;
        W = (w == 0) ? rel_w + ofs : (w == 1) ? root_w + ofs
          : (w == 2) ? pw1 + ofs : pw2 + ofs;
    }
    for (int item = threadIdx.x; item < 1024; item += 256) {
        int lane  = item & 31;
        int plane = (item >> 5) & 1;
        int ks    = (item >> 6) & 3;
        int p     = (item >> 8) & 3;
        uint32_t vals[4];
#pragma unroll
        for (int r = 0; r < 4; r++) {
            int n = p * 16 + ((r >> 1) ? 8 : 0) + (lane >> 2);
            int k = ks * 16 + ((lane & 3) << 1) + ((r & 1) ? 8 : 0);
            float a = W[(size_t)(kbase + k) * 64 + n];
            float b = W[(size_t)(kbase + k + 1) * 64 + n];
            uint32_t hi, lo;
            split2(a, b, hi, lo);
            vals[r] = plane ? lo : hi;
        }
        g_wfrag[t * 1024 + item] = make_uint4(vals[0], vals[1], vals[2], vals[3]);
    }
}

// ================= bucket build =================
__global__ void zero_cnt_kernel() {
    int i = blockIdx.x * blockDim.x + threadIdx.x;
    if (i < NN) g_cnt[i] = 0;
}
__global__ void fill_bucket_kernel(const int* __restrict__ ei) {
    int e = blockIdx.x * blockDim.x + threadIdx.x;
    if (e >= EE) return;
    int s = ei[e];
    int d = ei[EE + e];
    int pos = atomicAdd(&g_cnt[d], 1);
    if (pos < BK) g_bucket[((size_t)d << 7) + pos] = s;
}

// ================= aggregation: warp/node, lane = half2 column pair ========
// per edge: broadcast index + coalesced LDG.32 + HADD2  (~4 instr/edge)
__global__ void __launch_bounds__(256) agg_kernel() {
    int wid = (blockIdx.x * blockDim.x + threadIdx.x) >> 5;
    if (wid >= NN) return;
    int lane = threadIdx.x & 31;

    int deg = g_cnt[wid];
    int n = (deg < BK) ? deg : BK;
    const int* bkt = g_bucket + ((size_t)wid << 7);
    const __half2* hsrc = (const __half2*)g_h + lane;   // column pair 2*lane

    __half2 a0 = __floats2half2_rn(0.f, 0.f);
    __half2 a1 = __floats2half2_rn(0.f, 0.f);
    int e = 0;
    for (; e + 1 < n; e += 2) {
        int s0 = bkt[e];
        int s1 = bkt[e + 1];
        a0 = __hadd2(a0, hsrc[(size_t)s0 * 32]);
        a1 = __hadd2(a1, hsrc[(size_t)s1 * 32]);
    }
    if (e < n) {
        int s0 = bkt[e];
        a0 = __hadd2(a0, hsrc[(size_t)s0 * 32]);
    }
    float2 f0 = __half22float2(a0);
    float2 f1 = __half22float2(a1);
    float inv = 1.0f / fmaxf((float)deg, 1.0f);
    float rx = (f0.x + f1.x) * inv;
    float ry = (f0.y + f1.y) * inv;
    ((__half2*)g_agg)[(size_t)wid * 32 + lane] = __floats2half2_rn(rx, ry);
}

// ================= MMA + LDSM =================
__device__ __forceinline__ void mma_bf16(float* acc,
                                         uint32_t a0, uint32_t a1, uint32_t a2, uint32_t a3,
                                         uint32_t b0, uint32_t b1) {
    asm volatile(
        "mma.sync.aligned.m16n8k16.row.col.f32.bf16.bf16.f32 "
        "{%0,%1,%2,%3}, {%4,%5,%6,%7}, {%8,%9}, {%0,%1,%2,%3};"
        : "+f"(acc[0]), "+f"(acc[1]), "+f"(acc[2]), "+f"(acc[3])
        : "r"(a0), "r"(a1), "r"(a2), "r"(a3), "r"(b0), "r"(b1));
}

__device__ __forceinline__ void ldsm4(uint32_t addr,
                                      uint32_t& r0, uint32_t& r1,
                                      uint32_t& r2, uint32_t& r3) {
    asm volatile("ldmatrix.sync.aligned.m8n8.x4.shared.b16 {%0,%1,%2,%3}, [%4];"
                 : "=r"(r0), "=r"(r1), "=r"(r2), "=r"(r3) : "r"(addr));
}

// ================= A staging =================
__device__ __forceinline__ void stage_A_f32(char* sm, int plane_off,
                                            const float* __restrict__ A,
                                            int row0, int K, int kofs,
                                            int m0, int lane) {
    int r = m0 + (lane & 15);
    int cb = (lane >> 4) << 5;
    int row = row0 + r;
#pragma unroll
    for (int cc = 0; cc < 2; cc++) {
        int c0 = cb + cc * 16;
        float v[16];
        if (row < NN) {
            const float* src = A + (size_t)row * K + kofs + c0;
#pragma unroll
            for (int q = 0; q < 4; q++) {
                float4 f = *(const float4*)(src + q * 4);
                v[q * 4 + 0] = f.x; v[q * 4 + 1] = f.y;
                v[q * 4 + 2] = f.z; v[q * 4 + 3] = f.w;
            }
        } else {
#pragma unroll
            for (int q = 0; q < 16; q++) v[q] = 0.f;
        }
        uint4 h0, h1;
        h0.x = pack_bf2(v[0],  v[1]);  h0.y = pack_bf2(v[2],  v[3]);
        h0.z = pack_bf2(v[4],  v[5]);  h0.w = pack_bf2(v[6],  v[7]);
        h1.x = pack_bf2(v[8],  v[9]);  h1.y = pack_bf2(v[10], v[11]);
        h1.z = pack_bf2(v[12], v[13]); h1.w = pack_bf2(v[14], v[15]);
        char* ph = sm + plane_off + (size_t)r * SAB + c0 * 2;
        ((uint4*)ph)[0] = h0; ((uint4*)ph)[1] = h1;
    }
}

// fp16 source -> bf16 plane; K fixed at 64
__device__ __forceinline__ void stage_A_f16(char* sm, int plane_off,
                                            const __half* __restrict__ A,
                                            int row0, int m0, int lane) {
    int r = m0 + (lane & 15);
    int cb = (lane >> 4) << 5;
    int row = row0 + r;
#pragma unroll
    for (int cc = 0; cc < 2; cc++) {
        int c0 = cb + cc * 16;
        uint4 u = make_uint4(0, 0, 0, 0), u2 = make_uint4(0, 0, 0, 0);
        if (row < NN) {
            const uint4* src = (const uint4*)(A + (size_t)row * HH + c0);
            u = src[0];
            u2 = src[1];
        }
        uint4 h0, h1;
        h0.x = h2_to_bf2(u.x);  h0.y = h2_to_bf2(u.y);
        h0.z = h2_to_bf2(u.z);  h0.w = h2_to_bf2(u.w);
        h1.x = h2_to_bf2(u2.x); h1.y = h2_to_bf2(u2.y);
        h1.z = h2_to_bf2(u2.z); h1.w = h2_to_bf2(u2.w);
        char* ph = sm + plane_off + (size_t)r * SAB + c0 * 2;
        ((uint4*)ph)[0] = h0; ((uint4*)ph)[1] = h1;
    }
}

// ================= GEMM unit =================
__device__ __forceinline__ void gemm_unit_w(uint32_t smb, int plane_off, int t,
                                            float* acc, int m0, int lane) {
    const uint4* wf = g_wfrag + t * 1024 + lane;
    uint32_t a_addr = smb + plane_off
                    + (uint32_t)((m0 + (lane & 15)) * SAB + ((lane >> 4) << 4));

#pragma unroll
    for (int ks = 0; ks < 4; ks++) {
        uint32_t a0, a1, a2, a3;
        ldsm4(a_addr + ks * 32, a0, a1, a2, a3);
#pragma unroll
        for (int p = 0; p < 4; p++) {
            uint4 bh = wf[(p * 4 + ks) * 64];
            uint4 bl = wf[(p * 4 + ks) * 64 + 32];
            float* A0 = acc + (2 * p) * 4;
            float* A1 = acc + (2 * p + 1) * 4;
            mma_bf16(A0, a0, a1, a2, a3, bh.x, bh.y);
            mma_bf16(A1, a0, a1, a2, a3, bh.z, bh.w);
            mma_bf16(A0, a0, a1, a2, a3, bl.x, bl.y);
            mma_bf16(A1, a0, a1, a2, a3, bl.z, bl.w);
        }
    }
}

__device__ __forceinline__ void zero32(float* a) {
#pragma unroll
    for (int i = 0; i < 32; i++) a[i] = 0.f;
}

// epilogue -> bf16 plane 0 in smem
__device__ __forceinline__ void epi_to_A_w(char* sm, const float* acc,
                                           const float* __restrict__ bias,
                                           bool relu, int m0, int lane) {
    int g = lane >> 2, tg = lane & 3;
    size_t r0 = (size_t)(m0 + g) * SAB;
    size_t r1 = (size_t)(m0 + g + 8) * SAB;
#pragma unroll
    for (int j = 0; j < 8; j++) {
        int col = j * 8 + tg * 2;
        float b0 = __ldg(bias + col), b1 = __ldg(bias + col + 1);
        float v00 = acc[j * 4 + 0] + b0, v01 = acc[j * 4 + 1] + b1;
        float v10 = acc[j * 4 + 2] + b0, v11 = acc[j * 4 + 3] + b1;
        if (relu) {
            v00 = fmaxf(v00, 0.f); v01 = fmaxf(v01, 0.f);
            v10 = fmaxf(v10, 0.f); v11 = fmaxf(v11, 0.f);
        }
        *(uint32_t*)(sm + r0 + col * 2) = pack_bf2(v00, v01);
        *(uint32_t*)(sm + r1 + col * 2) = pack_bf2(v10, v11);
    }
}

// final epilogue -> fp16 g_h
__device__ __forceinline__ void epi_to_gmem_w(const float* acc,
                                              const float* __restrict__ bias,
                                              bool relu, int row0, int m0, int lane) {
    int g = lane >> 2, tg = lane & 3;
    int ra = row0 + m0 + g;
    int rb = ra + 8;
#pragma unroll
    for (int j = 0; j < 8; j++) {
        int col = j * 8 + tg * 2;
        float b0 = __ldg(bias + col), b1 = __ldg(bias + col + 1);
        float v00 = acc[j * 4 + 0] + b0, v01 = acc[j * 4 + 1] + b1;
        float v10 = acc[j * 4 + 2] + b0, v11 = acc[j * 4 + 3] + b1;
        if (relu) {
            v00 = fmaxf(v00, 0.f); v01 = fmaxf(v01, 0.f);
            v10 = fmaxf(v10, 0.f); v11 = fmaxf(v11, 0.f);
        }
        if (ra < NN)
            *(__half2*)(g_h + (size_t)ra * HH + col) = __floats2half2_rn(v00, v01);
        if (rb < NN)
            *(__half2*)(g_h + (size_t)rb * HH + col) = __floats2half2_rn(v10, v11);
    }
}

// ================= fused embed MLP =================
__global__ void __launch_bounds__(256, 3) embed_kernel(
    const float* __restrict__ x,
    const float* __restrict__ b1, const float* __restrict__ b2)
{
    extern __shared__ char sm[];
    uint32_t smb = (uint32_t)__cvta_generic_to_shared(sm);
    int lane = threadIdx.x & 31;
    int m0 = (threadIdx.x >> 5) * 16;
    int row0 = blockIdx.x * 128;

    stage_A_f32(sm, 0,     x, row0, DD, 0,  m0, lane);
    stage_A_f32(sm, PLANE, x, row0, DD, 64, m0, lane);
    __syncwarp();

    float acc[32];
    zero32(acc);
    gemm_unit_w(smb, 0,     0, acc, m0, lane);
    gemm_unit_w(smb, PLANE, 1, acc, m0, lane);
    __syncwarp();
    epi_to_A_w(sm, acc, b1, true, m0, lane);
    __syncwarp();

    zero32(acc);
    gemm_unit_w(smb, 0, 2, acc, m0, lane);
    epi_to_gmem_w(acc, b2, false, row0, m0, lane);
}

// ================= fused conv layer =================
__global__ void __launch_bounds__(256, 3) layer_kernel(
    int t0,
    const float* __restrict__ rb,
    const float* __restrict__ pb1,
    const float* __restrict__ pb2)
{
    extern __shared__ char sm[];
    uint32_t smb = (uint32_t)__cvta_generic_to_shared(sm);
    int lane = threadIdx.x & 31;
    int m0 = (threadIdx.x >> 5) * 16;
    int row0 = blockIdx.x * 128;

    stage_A_f16(sm, 0,     g_agg, row0, m0, lane);
    stage_A_f16(sm, PLANE, g_h,   row0, m0, lane);
    __syncwarp();

    float acc[32];
    zero32(acc);
    gemm_unit_w(smb, 0,     t0 + 0, acc, m0, lane);   // agg @ rel
    gemm_unit_w(smb, PLANE, t0 + 1, acc, m0, lane);   // += h @ root
    __syncwarp();
    epi_to_A_w(sm, acc, rb, false, m0, lane);         // h2
    __syncwarp();

    zero32(acc);
    gemm_unit_w(smb, 0, t0 + 2, acc, m0, lane);       // h2 @ pw1
    __syncwarp();
    epi_to_A_w(sm, acc, pb1, true, m0, lane);         // t
    __syncwarp();

    zero32(acc);
    gemm_unit_w(smb, 0, t0 + 3, acc, m0, lane);       // t @ pw2
    epi_to_gmem_w(acc, pb2, true, row0, m0, lane);    // h (fp16)
}

// ================= pooling + classifier =================
__device__ __forceinline__ int lbound(const int* a, int n, int v) {
    int lo = 0, hi = n;
    while (lo < hi) {
        int m = (lo + hi) >> 1;
        if (a[m] < v) lo = m + 1; else hi = m;
    }
    return lo;
}

__global__ void __launch_bounds__(256) pool_kernel(const int* __restrict__ batch) {
    __shared__ int s_lo, s_hi;
    __shared__ float sm[4][64];
    int g = blockIdx.x;
    int tid = threadIdx.x;
    if (tid == 0) {
        s_lo = lbound(batch, NN, g);
        s_hi = lbound(batch, NN, g + 1);
    }
    __syncthreads();
    int lo = s_lo, hi = s_hi;
    int col = tid & 63;
    int rg = tid >> 6;

    float acc = 0.f;
    for (int n = lo + rg; n < hi; n += 4)
        acc += __half2float(g_h[(size_t)n * HH + col]);
    sm[rg][col] = acc;
    __syncthreads();
    if (rg == 0) {
        float s = sm[0][col] + sm[1][col] + sm[2][col] + sm[3][col];
        float inv = 1.0f / fmaxf((float)(hi - lo), 1.0f);
        g_pooled[(size_t)g * HH + col] = s * inv;
    }
}

__global__ void cls_kernel(const float* __restrict__ W,
                           const float* __restrict__ b,
                           float* __restrict__ out)
{
    int tid = blockIdx.x * blockDim.x + threadIdx.x;
    if (tid >= GG * CC) return;
    int g = tid / CC;
    int c = tid % CC;
    float s = b[c];
#pragma unroll
    for (int k = 0; k < HH; k++)
        s += g_pooled[g * HH + k] * W[k * CC + c];
    out[tid] = s;
}

// ================= launcher =================
extern "C" void kernel_launch(void* const* d_in, const int* in_sizes, int n_in,
                              void* d_out, int out_size) {
    const float* x       = (const float*)d_in[0];
    const int*   ei      = (const int*)d_in[1];
    const int*   batch   = (const int*)d_in[2];
    const float* emb_w1  = (const float*)d_in[3];
    const float* emb_b1  = (const float*)d_in[4];
    const float* emb_w2  = (const float*)d_in[5];
    const float* emb_b2  = (const float*)d_in[6];
    const float* rel_w   = (const float*)d_in[7];
    const float* rel_b   = (const float*)d_in[8];
    const float* root_w  = (const float*)d_in[9];
    const float* post_w1 = (const float*)d_in[10];
    const float* post_b1 = (const float*)d_in[11];
    const float* post_w2 = (const float*)d_in[12];
    const float* post_b2 = (const float*)d_in[13];
    const float* cls_w   = (const float*)d_in[14];
    const float* cls_b   = (const float*)d_in[15];
    float*       out     = (float*)d_out;

    const int TB = 256;
    cudaFuncSetAttribute(embed_kernel, cudaFuncAttributeMaxDynamicSharedMemorySize, A_SMEM);
    cudaFuncSetAttribute(layer_kernel, cudaFuncAttributeMaxDynamicSharedMemorySize, A_SMEM);

    // ---- weight fragment prep + bucket build ----
    prep_wfrag_kernel<<<NT_W, 256>>>(emb_w1, emb_w2, rel_w, root_w, post_w1, post_w2);
    zero_cnt_kernel<<<(NN + TB - 1) / TB, TB>>>();
    fill_bucket_kernel<<<(EE + TB - 1) / TB, TB>>>(ei);

    // ---- embed ----
    embed_kernel<<<TILES128, 256, A_SMEM>>>(x, emb_b1, emb_b2);

    for (int l = 0; l < LL; l++) {
        agg_kernel<<<(NN * 32 + TB - 1) / TB, TB>>>();
        layer_kernel<<<TILES128, 256, A_SMEM>>>(
            3 + 4 * l,
            rel_b   + (size_t)l * HH,
            post_b1 + (size_t)l * HH,
            post_b2 + (size_t)l * HH);
    }

    // ---- mean pool + classifier ----
    pool_kernel<<<GG, 256>>>(batch);
    cls_kernel<<<(GG * CC + TB - 1) / TB, TB>>>(cls_w, cls_b, out);
}